// round 12
// baseline (speedup 1.0000x reference)
#include <cuda_runtime.h>
#include <cuda_bf16.h>

// Temporal-blocked heat stencil, packed-f32x2 register/shuffle edition, v8.
// Exact R8 geometry + buffers (the 631us kernel): 8 bands x 7 rows ->
// tile 128x56, halo 8, T=8, output 112x40, grid 14x38 = 532 blocks,
// 50 launches, a pre-scaled by DELTA_T, PW=1576/PH=1528.
// R11 (only change): the 7 forcing (a) loads are deferred until after step
// 0's __syncthreads(), so the front-batched LDG.128 count drops 14 -> 7
// (oe*MLP_p1 = 14 < Q_th=16), killing the cross-CTA L1tex-queue completion
// spread that inflates each launch's makespan.

#define HN 1501
#define PW 1576
#define PH 1528
#define PW4 (PW / 4)

#define ROWS 7
#define SH 56
#define HALO 8
#define TSTEPS 8
#define TX 112
#define TY 40
#define NBX 14
#define NBY 38
#define NLAUNCH 50

#define STEP_PARAM 0.225f
#define DELTA_T 1e-7f

typedef unsigned long long u64;

__device__ float4 g_U0[PW4 * PH];
__device__ float4 g_U1[PW4 * PH];
__device__ float4 g_A [PW4 * PH];

__device__ __forceinline__ u64 pk2(float lo, float hi) {
    u64 r; asm("mov.b64 %0, {%1, %2};" : "=l"(r) : "f"(lo), "f"(hi)); return r;
}
__device__ __forceinline__ void upk2(u64 v, float& lo, float& hi) {
    asm("mov.b64 {%0, %1}, %2;" : "=f"(lo), "=f"(hi) : "l"(v));
}
__device__ __forceinline__ u64 add2(u64 a, u64 b) {
    u64 r; asm("add.rn.f32x2 %0, %1, %2;" : "=l"(r) : "l"(a), "l"(b)); return r;
}
__device__ __forceinline__ u64 mul2(u64 a, u64 b) {
    u64 r; asm("mul.rn.f32x2 %0, %1, %2;" : "=l"(r) : "l"(a), "l"(b)); return r;
}
__device__ __forceinline__ u64 fma2(u64 a, u64 b, u64 c) {
    u64 r; asm("fma.rn.f32x2 %0, %1, %2, %3;" : "=l"(r) : "l"(a), "l"(b), "l"(c)); return r;
}

__global__ __launch_bounds__(256)
void stencil8_kernel(const float* __restrict__ srcP,
                     float* __restrict__ dstP,
                     const float* __restrict__ aP)
{
    __shared__ ulonglong2 sE[2][8][2][32];   // parity-double-buffered exchange rows

    const int tid  = threadIdx.x;
    const int lane = tid & 31;
    const int band = tid >> 5;
    const int y0   = band * ROWS;

    const int gx0 = blockIdx.x * TX - HALO;
    const int gy0 = blockIdx.y * TY - HALO;
    const int gx  = gx0 + lane * 4;

    const bool edgeBlock = (blockIdx.x == 0) || (blockIdx.x == NBX - 1) ||
                           (blockIdx.y == 0) || (blockIdx.y == NBY - 1);

    // ---- load u only (7 LDG.128 front batch), interleave pairs ----
    u64 uA[ROWS], uB[ROWS], aA[ROWS], aB[ROWS];
    const float4 Z = make_float4(0.f, 0.f, 0.f, 0.f);
#pragma unroll
    for (int r = 0; r < ROWS; r++) {
        int gy = gy0 + y0 + r;
        bool inb = (gx >= 0) && (gy >= 0);    // high side covered by padding
        float4 v = inb ? *reinterpret_cast<const float4*>(srcP + gy * PW + gx) : Z;
        uA[r] = pk2(v.x, v.z);
        uB[r] = pk2(v.y, v.w);
    }

    // Dirichlet masks (edge blocks only)
    const u64 mA = pk2((gx + 0 >= 1 && gx + 0 <= HN - 2) ? 1.f : 0.f,
                       (gx + 2 >= 1 && gx + 2 <= HN - 2) ? 1.f : 0.f);
    const u64 mB = pk2((gx + 1 >= 1 && gx + 1 <= HN - 2) ? 1.f : 0.f,
                       (gx + 3 >= 1 && gx + 3 <= HN - 2) ? 1.f : 0.f);
    float my[ROWS];
#pragma unroll
    for (int r = 0; r < ROWS; r++) {
        int gy = gy0 + y0 + r;
        my[r] = (gy >= 1 && gy <= HN - 2) ? 1.f : 0.f;
    }

    const u64 K225 = pk2(STEP_PARAM, STEP_PARAM);
    const u64 K01  = pk2(0.1f, 0.1f);

    // ---- 8 fused timesteps, single barrier per step ----
#pragma unroll 1
    for (int s = 0; s < TSTEPS; s++) {
        const int p = s & 1;

        sE[p][band][0][lane] = make_ulonglong2(uA[0], uB[0]);
        sE[p][band][1][lane] = make_ulonglong2(uA[ROWS - 1], uB[ROWS - 1]);
        __syncthreads();

        // Deferred forcing loads: issued after step 0's barrier (not hoistable
        // across BAR), overlapping with step-0 math instead of front-batching.
        if (s == 0) {
#pragma unroll
            for (int r = 0; r < ROWS; r++) {
                int gy = gy0 + y0 + r;
                bool inb = (gx >= 0) && (gy >= 0);
                float4 av = inb ? *reinterpret_cast<const float4*>(aP + gy * PW + gx) : Z;
                aA[r] = pk2(av.x, av.z);     // pre-scaled by DELTA_T at copy-in
                aB[r] = pk2(av.y, av.w);
            }
        }

        ulonglong2 upP = (band > 0) ? sE[p][band - 1][1][lane]
                                    : make_ulonglong2(uA[0], uB[0]);
        ulonglong2 dnP = (band < 7) ? sE[p][band + 1][0][lane]
                                    : make_ulonglong2(uA[ROWS - 1], uB[ROWS - 1]);

        u64 prevA = upP.x, prevB = upP.y;
#pragma unroll
        for (int r = 0; r < ROWS; r++) {
            u64 A = uA[r], B = uB[r];
            u64 nxA = (r < ROWS - 1) ? uA[r + 1] : dnP.x;
            u64 nxB = (r < ROWS - 1) ? uB[r + 1] : dnP.y;

            float c0, c2, c1, c3;
            upk2(A, c0, c2);
            upk2(B, c1, c3);

            float lf = __shfl_up_sync(0xffffffffu, c3, 1);
            float rt = __shfl_down_sync(0xffffffffu, c0, 1);

            u64 VA = add2(prevA, nxA);
            u64 VB = add2(prevB, nxB);
            u64 HA = add2(pk2(lf, c1), B);      // (lf+c1, c1+c3)
            u64 HB = add2(A, pk2(c2, rt));      // (c0+c2, c2+rt)

            u64 smA = add2(VA, HA);
            u64 smB = add2(VB, HB);

            u64 unA = fma2(K225, smA, fma2(K01, A, aA[r]));
            u64 unB = fma2(K225, smB, fma2(K01, B, aB[r]));

            if (edgeBlock) {
                u64 mr = pk2(my[r], my[r]);
                unA = mul2(mul2(unA, mA), mr);
                unB = mul2(mul2(unB, mB), mr);
            }

            prevA = A; prevB = B;
            uA[r] = unA; uB[r] = unB;
        }
        // no trailing barrier: parity buffers + next step's barrier order
        // step-s readers of sE[p] before step-(s+2) writers of sE[p].
    }

    // ---- store output region (rows 8..47, cols 8..119), de-interleave ----
    if (lane >= 2 && lane < 30) {
#pragma unroll
        for (int r = 0; r < ROWS; r++) {
            int y = y0 + r;
            if (y >= HALO && y < HALO + TY) {
                int gy = gy0 + y;
                float o0, o1, o2, o3;
                upk2(uA[r], o0, o2);
                upk2(uB[r], o1, o3);
                *reinterpret_cast<float4*>(dstP + gy * PW + gx) =
                    make_float4(o0, o1, o2, o3);
            }
        }
    }
}

__global__ __launch_bounds__(256)
void copy_in_kernel(const float* __restrict__ u0, const float* __restrict__ a)
{
    int j = blockIdx.x * blockDim.x + threadIdx.x;
    int i = blockIdx.y;
    if (j >= HN) return;
    float* U = reinterpret_cast<float*>(g_U0);
    float* A = reinterpret_cast<float*>(g_A);
    U[i * PW + j] = u0[i * HN + j];
    A[i * PW + j] = DELTA_T * a[i * HN + j];   // pre-scale forcing
}

__global__ __launch_bounds__(256)
void copy_out_kernel(float* __restrict__ out)
{
    int j = blockIdx.x * blockDim.x + threadIdx.x;
    int i = blockIdx.y;
    if (j >= HN) return;
    const float* U = reinterpret_cast<const float*>(g_U0);
    out[i * HN + j] = U[i * PW + j];
}

extern "C" void kernel_launch(void* const* d_in, const int* in_sizes, int n_in,
                              void* d_out, int out_size)
{
    const float* u0 = (const float*)d_in[0];
    const float* a  = (const float*)d_in[1];
    float* out = (float*)d_out;

    float *U0, *U1, *A;
    cudaGetSymbolAddress((void**)&U0, g_U0);
    cudaGetSymbolAddress((void**)&U1, g_U1);
    cudaGetSymbolAddress((void**)&A,  g_A);

    dim3 cgrid((HN + 255) / 256, HN);
    copy_in_kernel<<<cgrid, 256>>>(u0, a);

    dim3 sgrid(NBX, NBY);
    for (int l = 0; l < NLAUNCH; l++) {
        const float* src = (l & 1) ? U1 : U0;
        float*       dst = (l & 1) ? U0 : U1;
        stencil8_kernel<<<sgrid, 256>>>(src, dst, A);
    }
    // NLAUNCH even -> final state back in g_U0

    copy_out_kernel<<<cgrid, 256>>>(out);
}

// round 13
// speedup vs baseline: 1.2791x; 1.2791x over previous
#include <cuda_runtime.h>
#include <cuda_bf16.h>

// Temporal-blocked heat stencil, packed-f32x2 register/shuffle edition, v9.
// R12: occupancy via structural state-thinning — 512-thread blocks,
// 16 bands x 4 rows -> tile 128x64, halo 8, T=8, output 112x48,
// grid 14x32 = 448 blocks, 50 launches. Per-thread state 16 u64 -> ~60 regs
// -> 2 CTAs x 512 = 32 warps/SM (2x the 631us kernel's latency hiding).
// Inner row-step instruction recipe identical to R8. PW unchanged (1576).

#define HN 1501
#define PW 1576
#define PH 1544
#define PW4 (PW / 4)

#define ROWS 4
#define BANDS 16
#define THREADS 512
#define SH 64            // BANDS * ROWS
#define HALO 8
#define TSTEPS 8
#define TX 112
#define TY 48            // SH - 2*HALO
#define NBX 14           // 14*112 = 1568 >= 1501
#define NBY 32           // 32*48  = 1536 >= 1501
#define NLAUNCH 50

#define STEP_PARAM 0.225f
#define DELTA_T 1e-7f

typedef unsigned long long u64;

__device__ float4 g_U0[PW4 * PH];
__device__ float4 g_U1[PW4 * PH];
__device__ float4 g_A [PW4 * PH];

__device__ __forceinline__ u64 pk2(float lo, float hi) {
    u64 r; asm("mov.b64 %0, {%1, %2};" : "=l"(r) : "f"(lo), "f"(hi)); return r;
}
__device__ __forceinline__ void upk2(u64 v, float& lo, float& hi) {
    asm("mov.b64 {%0, %1}, %2;" : "=f"(lo), "=f"(hi) : "l"(v));
}
__device__ __forceinline__ u64 add2(u64 a, u64 b) {
    u64 r; asm("add.rn.f32x2 %0, %1, %2;" : "=l"(r) : "l"(a), "l"(b)); return r;
}
__device__ __forceinline__ u64 mul2(u64 a, u64 b) {
    u64 r; asm("mul.rn.f32x2 %0, %1, %2;" : "=l"(r) : "l"(a), "l"(b)); return r;
}
__device__ __forceinline__ u64 fma2(u64 a, u64 b, u64 c) {
    u64 r; asm("fma.rn.f32x2 %0, %1, %2, %3;" : "=l"(r) : "l"(a), "l"(b), "l"(c)); return r;
}

__global__ __launch_bounds__(THREADS, 2)
void stencil8_kernel(const float* __restrict__ srcP,
                     float* __restrict__ dstP,
                     const float* __restrict__ aP)
{
    __shared__ ulonglong2 sE[2][BANDS][2][32];   // 32 KB, parity double-buffered

    const int tid  = threadIdx.x;
    const int lane = tid & 31;
    const int band = tid >> 5;          // 0..15
    const int y0   = band * ROWS;

    const int gx0 = blockIdx.x * TX - HALO;
    const int gy0 = blockIdx.y * TY - HALO;
    const int gx  = gx0 + lane * 4;

    const bool edgeBlock = (blockIdx.x == 0) || (blockIdx.x == NBX - 1) ||
                           (blockIdx.y == 0) || (blockIdx.y == NBY - 1);

    // ---- load u + (pre-scaled) forcing, interleave into (c0,c2)/(c1,c3) ----
    u64 uA[ROWS], uB[ROWS], aA[ROWS], aB[ROWS];
    const float4 Z = make_float4(0.f, 0.f, 0.f, 0.f);
#pragma unroll
    for (int r = 0; r < ROWS; r++) {
        int gy = gy0 + y0 + r;
        bool inb = (gx >= 0) && (gy >= 0);    // high side covered by padding
        float4 v = Z, av = Z;
        if (inb) {
            v  = *reinterpret_cast<const float4*>(srcP + gy * PW + gx);
            av = *reinterpret_cast<const float4*>(aP   + gy * PW + gx);
        }
        uA[r] = pk2(v.x, v.z);
        uB[r] = pk2(v.y, v.w);
        aA[r] = pk2(av.x, av.z);     // already scaled by DELTA_T at copy-in
        aB[r] = pk2(av.y, av.w);
    }

    // Dirichlet masks (edge blocks only)
    const u64 mA = pk2((gx + 0 >= 1 && gx + 0 <= HN - 2) ? 1.f : 0.f,
                       (gx + 2 >= 1 && gx + 2 <= HN - 2) ? 1.f : 0.f);
    const u64 mB = pk2((gx + 1 >= 1 && gx + 1 <= HN - 2) ? 1.f : 0.f,
                       (gx + 3 >= 1 && gx + 3 <= HN - 2) ? 1.f : 0.f);
    float my[ROWS];
#pragma unroll
    for (int r = 0; r < ROWS; r++) {
        int gy = gy0 + y0 + r;
        my[r] = (gy >= 1 && gy <= HN - 2) ? 1.f : 0.f;
    }

    const u64 K225 = pk2(STEP_PARAM, STEP_PARAM);
    const u64 K01  = pk2(0.1f, 0.1f);

    // ---- 8 fused timesteps, single barrier per step ----
#pragma unroll 1
    for (int s = 0; s < TSTEPS; s++) {
        const int p = s & 1;

        sE[p][band][0][lane] = make_ulonglong2(uA[0], uB[0]);
        sE[p][band][1][lane] = make_ulonglong2(uA[ROWS - 1], uB[ROWS - 1]);
        __syncthreads();

        ulonglong2 upP = (band > 0) ? sE[p][band - 1][1][lane]
                                    : make_ulonglong2(uA[0], uB[0]);
        ulonglong2 dnP = (band < BANDS - 1) ? sE[p][band + 1][0][lane]
                                    : make_ulonglong2(uA[ROWS - 1], uB[ROWS - 1]);

        u64 prevA = upP.x, prevB = upP.y;
#pragma unroll
        for (int r = 0; r < ROWS; r++) {
            u64 A = uA[r], B = uB[r];
            u64 nxA = (r < ROWS - 1) ? uA[r + 1] : dnP.x;
            u64 nxB = (r < ROWS - 1) ? uB[r + 1] : dnP.y;

            float c0, c2, c1, c3;
            upk2(A, c0, c2);
            upk2(B, c1, c3);

            float lf = __shfl_up_sync(0xffffffffu, c3, 1);
            float rt = __shfl_down_sync(0xffffffffu, c0, 1);

            u64 VA = add2(prevA, nxA);
            u64 VB = add2(prevB, nxB);
            u64 HA = add2(pk2(lf, c1), B);      // (lf+c1, c1+c3)
            u64 HB = add2(A, pk2(c2, rt));      // (c0+c2, c2+rt)

            u64 smA = add2(VA, HA);
            u64 smB = add2(VB, HB);

            u64 unA = fma2(K225, smA, fma2(K01, A, aA[r]));
            u64 unB = fma2(K225, smB, fma2(K01, B, aB[r]));

            if (edgeBlock) {
                u64 mr = pk2(my[r], my[r]);
                unA = mul2(mul2(unA, mA), mr);
                unB = mul2(mul2(unB, mB), mr);
            }

            prevA = A; prevB = B;
            uA[r] = unA; uB[r] = unB;
        }
        // no trailing barrier: parity buffers + next step's barrier order
        // step-s readers of sE[p] before step-(s+2) writers of sE[p].
    }

    // ---- store output region (tile rows 8..55, cols 8..119) ----
    if (lane >= 2 && lane < 30) {
#pragma unroll
        for (int r = 0; r < ROWS; r++) {
            int y = y0 + r;
            if (y >= HALO && y < HALO + TY) {
                int gy = gy0 + y;
                float o0, o1, o2, o3;
                upk2(uA[r], o0, o2);
                upk2(uB[r], o1, o3);
                *reinterpret_cast<float4*>(dstP + gy * PW + gx) =
                    make_float4(o0, o1, o2, o3);
            }
        }
    }
}

__global__ __launch_bounds__(256)
void copy_in_kernel(const float* __restrict__ u0, const float* __restrict__ a)
{
    int j = blockIdx.x * blockDim.x + threadIdx.x;
    int i = blockIdx.y;
    if (j >= HN) return;
    float* U = reinterpret_cast<float*>(g_U0);
    float* A = reinterpret_cast<float*>(g_A);
    U[i * PW + j] = u0[i * HN + j];
    A[i * PW + j] = DELTA_T * a[i * HN + j];   // pre-scale forcing
}

__global__ __launch_bounds__(256)
void copy_out_kernel(float* __restrict__ out)
{
    int j = blockIdx.x * blockDim.x + threadIdx.x;
    int i = blockIdx.y;
    if (j >= HN) return;
    const float* U = reinterpret_cast<const float*>(g_U0);
    out[i * HN + j] = U[i * PW + j];
}

extern "C" void kernel_launch(void* const* d_in, const int* in_sizes, int n_in,
                              void* d_out, int out_size)
{
    const float* u0 = (const float*)d_in[0];
    const float* a  = (const float*)d_in[1];
    float* out = (float*)d_out;

    float *U0, *U1, *A;
    cudaGetSymbolAddress((void**)&U0, g_U0);
    cudaGetSymbolAddress((void**)&U1, g_U1);
    cudaGetSymbolAddress((void**)&A,  g_A);

    dim3 cgrid((HN + 255) / 256, HN);
    copy_in_kernel<<<cgrid, 256>>>(u0, a);

    dim3 sgrid(NBX, NBY);
    for (int l = 0; l < NLAUNCH; l++) {
        const float* src = (l & 1) ? U1 : U0;
        float*       dst = (l & 1) ? U0 : U1;
        stencil8_kernel<<<sgrid, THREADS>>>(src, dst, A);
    }
    // NLAUNCH even -> final state back in g_U0

    copy_out_kernel<<<cgrid, 256>>>(out);
}